// round 3
// baseline (speedup 1.0000x reference)
#include <cuda_runtime.h>

#define THREADS 256

// ---- shared memory layout (float indices) ----
#define XO_OFF    0                       // x tile / attention output  [49][192]
#define Q_OFF     9408                    // q [49][192]
#define K_OFF     18816                   // k [49][192]
#define V_OFF     28224                   // v [49][192]
#define WT_OFF    37632                   // W tile [16][WT_STRIDE]
#define WT_STRIDE 194                     // padded (even, conflict-free)
#define COS_OFF   (WT_OFF + 16 * WT_STRIDE)   // 40736, [49*6][16]
#define SIN_OFF   (COS_OFF + 4704)            // 45440
#define LG_OFF    (SIN_OFF + 4704)            // 50144, logits [49][LG_STRIDE]
#define LG_STRIDE 52
#define SMEM_FLOATS (LG_OFF + 49 * LG_STRIDE) // 52692
#define SMEM_BYTES  (SMEM_FLOATS * 4)         // 210768 bytes < 227KB

// ---- packed f32x2 helpers (Blackwell FFMA2: 2x fp32 FMA rate) ----
__device__ __forceinline__ unsigned long long pk2(float lo, float hi) {
    unsigned long long r;
    asm("mov.b64 %0, {%1, %2};" : "=l"(r) : "f"(lo), "f"(hi));
    return r;
}
__device__ __forceinline__ float2 unpk2(unsigned long long v) {
    float2 r;
    asm("mov.b64 {%0, %1}, %2;" : "=f"(r.x), "=f"(r.y) : "l"(v));
    return r;
}
__device__ __forceinline__ void fma2(unsigned long long& d, unsigned long long a,
                                     unsigned long long b) {
    asm("fma.rn.f32x2 %0, %1, %2, %0;" : "+l"(d) : "l"(a), "l"(b));
}

// C[49][192] = A[49][192] (smem, in_off) x W^T  (W is [192 rows][192 cols] row-major, dot over cols)
// out[r][j] = (sum_c A[r][c] * W[j][c] + bias[j]) * scale   -> smem at out_off
// Thread map: ty = tid/32 owns rows {ty+8i}, tx = tid%32 owns col pairs {2tx+64m}.
__device__ __noinline__ void gemm192(const float* __restrict__ W,
                                     const float* __restrict__ bias,
                                     int in_off, int out_off, float scale)
{
    extern __shared__ float sm[];
    const int tid = threadIdx.x;
    const int ty = tid >> 5;
    const int tx = tid & 31;

    unsigned long long acc[7][3];
    #pragma unroll
    for (int i = 0; i < 7; i++)
        #pragma unroll
        for (int m = 0; m < 3; m++) acc[i][m] = 0ULL;

    for (int kc = 0; kc < 192; kc += 16) {
        __syncthreads();   // previous consumers of WT done
        // stage W[0:192][kc:kc+16] transposed into wt[kk][j]
        #pragma unroll
        for (int i = 0; i < 3; i++) {
            int li = tid + i * 256;           // 768 float4 loads
            int j  = li >> 2;                 // 0..191
            int kb = (li & 3) << 2;           // 0,4,8,12
            float4 wv = *reinterpret_cast<const float4*>(&W[j * 192 + kc + kb]);
            sm[WT_OFF + (kb + 0) * WT_STRIDE + j] = wv.x;
            sm[WT_OFF + (kb + 1) * WT_STRIDE + j] = wv.y;
            sm[WT_OFF + (kb + 2) * WT_STRIDE + j] = wv.z;
            sm[WT_OFF + (kb + 3) * WT_STRIDE + j] = wv.w;
        }
        __syncthreads();
        #pragma unroll
        for (int kk = 0; kk < 16; kk++) {
            unsigned long long bv[3];
            #pragma unroll
            for (int m = 0; m < 3; m++)
                bv[m] = *reinterpret_cast<const unsigned long long*>(
                    &sm[WT_OFF + kk * WT_STRIDE + 2 * tx + 64 * m]);
            #pragma unroll
            for (int i = 0; i < 7; i++) {
                int r = ty + 8 * i;
                float a = (r < 49) ? sm[in_off + r * 192 + kc + kk] : 0.0f;
                unsigned long long a2 = pk2(a, a);
                #pragma unroll
                for (int m = 0; m < 3; m++) fma2(acc[i][m], a2, bv[m]);
            }
        }
    }
    #pragma unroll
    for (int i = 0; i < 7; i++) {
        int r = ty + 8 * i;
        if (r < 49) {
            #pragma unroll
            for (int m = 0; m < 3; m++) {
                int j = 2 * tx + 64 * m;
                float2 av = unpk2(acc[i][m]);
                float2 bb = *reinterpret_cast<const float2*>(&bias[j]);
                float2 o;
                o.x = (av.x + bb.x) * scale;
                o.y = (av.y + bb.y) * scale;
                *reinterpret_cast<float2*>(&sm[out_off + r * 192 + j]) = o;
            }
        }
    }
}

__global__ void __launch_bounds__(THREADS, 1)
swin_fused_kernel(const float* __restrict__ x,
                  const float* __restrict__ mask,
                  const float* __restrict__ qkv_w,
                  const float* __restrict__ qkv_b,
                  const float* __restrict__ proj_w,
                  const float* __restrict__ proj_b,
                  const float* __restrict__ rope,
                  float* __restrict__ out)
{
    extern __shared__ float sm[];
    const int tid = threadIdx.x;
    const int b = blockIdx.x;

    // load x tile [49][192] (2352 float4s)
    {
        const float4* xg = reinterpret_cast<const float4*>(x) + (size_t)b * 2352;
        float4* xs = reinterpret_cast<float4*>(&sm[XO_OFF]);
        #pragma unroll
        for (int i = 0; i < 10; i++) {
            int idx = tid + i * 256;
            if (idx < 2352) xs[idx] = xg[idx];
        }
    }
    // rope cos/sin tables: layout [(n*6+h)*16 + d]
    for (int i = tid; i < 4704; i += THREADS) {
        int d = i & 15, nh = i >> 4;
        int hh = nh % 6, n = nh / 6;
        float fx = rope[hh * 16 + d];
        float fy = rope[96 + hh * 16 + d];
        float ang = (float)(n % 7) * fx + (float)(n / 7) * fy;
        float sv, cv;
        sincosf(ang, &sv, &cv);
        sm[COS_OFF + i] = cv;
        sm[SIN_OFF + i] = sv;
    }

    // QKV projections (scale folded into q, matching (xW+b)*scale)
    gemm192(qkv_w,         qkv_b,       XO_OFF, Q_OFF, 0.17677669529663687f);
    gemm192(qkv_w + 36864, qkv_b + 192, XO_OFF, K_OFF, 1.0f);
    gemm192(qkv_w + 73728, qkv_b + 384, XO_OFF, V_OFF, 1.0f);
    __syncthreads();

    // RoPE on q and k: (even,odd) pair rotation
    for (int i = tid; i < 4704; i += THREADS) {
        int d = i & 15, nh = i >> 4;
        int hh = nh % 6, n = nh / 6;
        int base = n * 192 + hh * 32 + 2 * d;
        float cv = sm[COS_OFF + i], sv = sm[SIN_OFF + i];
        float2 qu = *reinterpret_cast<float2*>(&sm[Q_OFF + base]);
        float2 ku = *reinterpret_cast<float2*>(&sm[K_OFF + base]);
        float2 qo = make_float2(qu.x * cv - qu.y * sv, qu.x * sv + qu.y * cv);
        float2 ko = make_float2(ku.x * cv - ku.y * sv, ku.x * sv + ku.y * cv);
        *reinterpret_cast<float2*>(&sm[Q_OFF + base]) = qo;
        *reinterpret_cast<float2*>(&sm[K_OFF + base]) = ko;
    }

    const float* mrow = mask + (size_t)(b & 63) * 2401;  // window = b % NW

    for (int hh = 0; hh < 6; hh++) {
        __syncthreads();  // rope done (h=0) / prev head's P@V read of LG done
        // logits[49][49] = q_h @ k_h^T + mask, 2x2 register tiles
        for (int bi = tid; bi < 625; bi += THREADS) {
            int ni = (bi / 25) * 2;
            int mi = (bi % 25) * 2;
            const float4* q0 = reinterpret_cast<const float4*>(&sm[Q_OFF + ni * 192 + hh * 32]);
            const float4* q1 = reinterpret_cast<const float4*>(&sm[Q_OFF + (ni + 1) * 192 + hh * 32]);
            const float4* k0 = reinterpret_cast<const float4*>(&sm[K_OFF + mi * 192 + hh * 32]);
            const float4* k1 = reinterpret_cast<const float4*>(&sm[K_OFF + (mi + 1) * 192 + hh * 32]);
            float a00 = 0.f, a01 = 0.f, a10 = 0.f, a11 = 0.f;
            #pragma unroll
            for (int d4 = 0; d4 < 8; d4++) {
                float4 qa = q0[d4], qb = q1[d4], ka = k0[d4], kb = k1[d4];
                a00 += qa.x * ka.x + qa.y * ka.y + qa.z * ka.z + qa.w * ka.w;
                a01 += qa.x * kb.x + qa.y * kb.y + qa.z * kb.z + qa.w * kb.w;
                a10 += qb.x * ka.x + qb.y * ka.y + qb.z * ka.z + qb.w * ka.w;
                a11 += qb.x * kb.x + qb.y * kb.y + qb.z * kb.z + qb.w * kb.w;
            }
            bool n1ok = (ni + 1) < 49;
            bool m1ok = (mi + 1) < 49;
            sm[LG_OFF + ni * LG_STRIDE + mi] = a00 + mrow[ni * 49 + mi];
            if (m1ok)         sm[LG_OFF + ni * LG_STRIDE + mi + 1]       = a01 + mrow[ni * 49 + mi + 1];
            if (n1ok)         sm[LG_OFF + (ni + 1) * LG_STRIDE + mi]     = a10 + mrow[(ni + 1) * 49 + mi];
            if (n1ok && m1ok) sm[LG_OFF + (ni + 1) * LG_STRIDE + mi + 1] = a11 + mrow[(ni + 1) * 49 + mi + 1];
        }
        __syncthreads();
        // softmax: one thread per row
        if (tid < 49) {
            float* row = &sm[LG_OFF + tid * LG_STRIDE];
            float mx = row[0];
            #pragma unroll 7
            for (int m = 1; m < 49; m++) mx = fmaxf(mx, row[m]);
            float s = 0.f;
            #pragma unroll 7
            for (int m = 0; m < 49; m++) { float e = __expf(row[m] - mx); row[m] = e; s += e; }
            float inv = 1.0f / s;
            #pragma unroll 7
            for (int m = 0; m < 49; m++) row[m] *= inv;
        }
        __syncthreads();
        // out_h[49][32] = P @ V_h  -> write into XO (x no longer needed)
        {
            int dp = tid & 15;   // d = 2*dp
            int nb = tid >> 4;
            #pragma unroll
            for (int t = 0; t < 4; t++) {
                int n = nb + 16 * t;
                if (n < 49) {
                    unsigned long long accv = 0ULL;
                    const float* pr = &sm[LG_OFF + n * LG_STRIDE];
                    const float* vp = &sm[V_OFF + hh * 32 + 2 * dp];
                    #pragma unroll 7
                    for (int m = 0; m < 49; m++) {
                        unsigned long long p2 = pk2(pr[m], pr[m]);
                        unsigned long long vv =
                            *reinterpret_cast<const unsigned long long*>(&vp[m * 192]);
                        fma2(accv, p2, vv);
                    }
                    float2 r = unpk2(accv);
                    *reinterpret_cast<float2*>(&sm[XO_OFF + n * 192 + hh * 32 + 2 * dp]) = r;
                }
            }
        }
    }

    // output projection: XO @ proj_w^T + proj_b -> reuse Q buffer
    gemm192(proj_w, proj_b, XO_OFF, Q_OFF, 1.0f);
    __syncthreads();
    {
        float4* og = reinterpret_cast<float4*>(out) + (size_t)b * 2352;
        const float4* qs = reinterpret_cast<const float4*>(&sm[Q_OFF]);
        for (int i = tid; i < 2352; i += THREADS) og[i] = qs[i];
    }
}

extern "C" void kernel_launch(void* const* d_in, const int* in_sizes, int n_in,
                              void* d_out, int out_size) {
    const float* x      = (const float*)d_in[0];
    const float* mask   = (const float*)d_in[1];
    const float* qkv_w  = (const float*)d_in[2];
    const float* qkv_b  = (const float*)d_in[3];
    const float* proj_w = (const float*)d_in[4];
    const float* proj_b = (const float*)d_in[5];
    const float* rope   = (const float*)d_in[6];
    float* out = (float*)d_out;

    cudaFuncSetAttribute(swin_fused_kernel,
                         cudaFuncAttributeMaxDynamicSharedMemorySize, SMEM_BYTES);
    swin_fused_kernel<<<4096, THREADS, SMEM_BYTES>>>(
        x, mask, qkv_w, qkv_b, proj_w, proj_b, rope, out);
}

// round 4
// speedup vs baseline: 1.0006x; 1.0006x over previous
#include <cuda_runtime.h>

#define THREADS 256

// ---- shared memory layout (float indices) ----
#define XO_OFF    0                       // x tile / attention output  [49][192]
#define Q_OFF     9408                    // q [49][192]
#define K_OFF     18816                   // k [49][192]
#define V_OFF     28224                   // v [49][192]
#define WT_OFF    37632                   // W tile [16][WT_STRIDE]
#define WT_STRIDE 194                     // padded (even, conflict-free)
#define COS_OFF   (WT_OFF + 16 * WT_STRIDE)   // 40736, [49*6][16]
#define SIN_OFF   (COS_OFF + 4704)            // 45440
#define LG_OFF    (SIN_OFF + 4704)            // 50144, logits [49][LG_STRIDE]
#define LG_STRIDE 52
#define SMEM_FLOATS (LG_OFF + 49 * LG_STRIDE) // 52692
#define SMEM_BYTES  (SMEM_FLOATS * 4)         // 210768 bytes < 227KB

// ---- packed f32x2 helpers (Blackwell FFMA2: 2x fp32 FMA rate) ----
__device__ __forceinline__ unsigned long long pk2(float lo, float hi) {
    unsigned long long r;
    asm("mov.b64 %0, {%1, %2};" : "=l"(r) : "f"(lo), "f"(hi));
    return r;
}
__device__ __forceinline__ float2 unpk2(unsigned long long v) {
    float2 r;
    asm("mov.b64 {%0, %1}, %2;" : "=f"(r.x), "=f"(r.y) : "l"(v));
    return r;
}
__device__ __forceinline__ void fma2(unsigned long long& d, unsigned long long a,
                                     unsigned long long b) {
    asm("fma.rn.f32x2 %0, %1, %2, %0;" : "+l"(d) : "l"(a), "l"(b));
}

// C[49][192] = A[49][192] (smem, in_off) x W^T  (W is [192 rows][192 cols] row-major, dot over cols)
// out[r][j] = (sum_c A[r][c] * W[j][c] + bias[j]) * scale   -> smem at out_off
// Thread map: ty = tid/32 owns rows {ty+8i}, tx = tid%32 owns col pairs {2tx+64m}.
__device__ __noinline__ void gemm192(const float* __restrict__ W,
                                     const float* __restrict__ bias,
                                     int in_off, int out_off, float scale)
{
    extern __shared__ float sm[];
    const int tid = threadIdx.x;
    const int ty = tid >> 5;
    const int tx = tid & 31;

    unsigned long long acc[7][3];
    #pragma unroll
    for (int i = 0; i < 7; i++)
        #pragma unroll
        for (int m = 0; m < 3; m++) acc[i][m] = 0ULL;

    for (int kc = 0; kc < 192; kc += 16) {
        __syncthreads();   // previous consumers of WT done
        // stage W[0:192][kc:kc+16] transposed into wt[kk][j]
        #pragma unroll
        for (int i = 0; i < 3; i++) {
            int li = tid + i * 256;           // 768 float4 loads
            int j  = li >> 2;                 // 0..191
            int kb = (li & 3) << 2;           // 0,4,8,12
            float4 wv = *reinterpret_cast<const float4*>(&W[j * 192 + kc + kb]);
            sm[WT_OFF + (kb + 0) * WT_STRIDE + j] = wv.x;
            sm[WT_OFF + (kb + 1) * WT_STRIDE + j] = wv.y;
            sm[WT_OFF + (kb + 2) * WT_STRIDE + j] = wv.z;
            sm[WT_OFF + (kb + 3) * WT_STRIDE + j] = wv.w;
        }
        __syncthreads();
        #pragma unroll
        for (int kk = 0; kk < 16; kk++) {
            unsigned long long bv[3];
            #pragma unroll
            for (int m = 0; m < 3; m++)
                bv[m] = *reinterpret_cast<const unsigned long long*>(
                    &sm[WT_OFF + kk * WT_STRIDE + 2 * tx + 64 * m]);
            #pragma unroll
            for (int i = 0; i < 7; i++) {
                int r = ty + 8 * i;
                float a = (r < 49) ? sm[in_off + r * 192 + kc + kk] : 0.0f;
                unsigned long long a2 = pk2(a, a);
                #pragma unroll
                for (int m = 0; m < 3; m++) fma2(acc[i][m], a2, bv[m]);
            }
        }
    }
    #pragma unroll
    for (int i = 0; i < 7; i++) {
        int r = ty + 8 * i;
        if (r < 49) {
            #pragma unroll
            for (int m = 0; m < 3; m++) {
                int j = 2 * tx + 64 * m;
                float2 av = unpk2(acc[i][m]);
                float2 bb = *reinterpret_cast<const float2*>(&bias[j]);
                float2 o;
                o.x = (av.x + bb.x) * scale;
                o.y = (av.y + bb.y) * scale;
                *reinterpret_cast<float2*>(&sm[out_off + r * 192 + j]) = o;
            }
        }
    }
}

__global__ void __launch_bounds__(THREADS, 1)
swin_fused_kernel(const float* __restrict__ x,
                  const float* __restrict__ mask,
                  const float* __restrict__ qkv_w,
                  const float* __restrict__ qkv_b,
                  const float* __restrict__ proj_w,
                  const float* __restrict__ proj_b,
                  const float* __restrict__ rope,
                  float* __restrict__ out)
{
    extern __shared__ float sm[];
    const int tid = threadIdx.x;
    const int b = blockIdx.x;

    // load x tile [49][192] (2352 float4s)
    {
        const float4* xg = reinterpret_cast<const float4*>(x) + (size_t)b * 2352;
        float4* xs = reinterpret_cast<float4*>(&sm[XO_OFF]);
        #pragma unroll
        for (int i = 0; i < 10; i++) {
            int idx = tid + i * 256;
            if (idx < 2352) xs[idx] = xg[idx];
        }
    }
    // rope cos/sin tables: layout [(n*6+h)*16 + d]
    for (int i = tid; i < 4704; i += THREADS) {
        int d = i & 15, nh = i >> 4;
        int hh = nh % 6, n = nh / 6;
        float fx = rope[hh * 16 + d];
        float fy = rope[96 + hh * 16 + d];
        float ang = (float)(n % 7) * fx + (float)(n / 7) * fy;
        float sv, cv;
        sincosf(ang, &sv, &cv);
        sm[COS_OFF + i] = cv;
        sm[SIN_OFF + i] = sv;
    }

    // QKV projections (scale folded into q, matching (xW+b)*scale)
    gemm192(qkv_w,         qkv_b,       XO_OFF, Q_OFF, 0.17677669529663687f);
    gemm192(qkv_w + 36864, qkv_b + 192, XO_OFF, K_OFF, 1.0f);
    gemm192(qkv_w + 73728, qkv_b + 384, XO_OFF, V_OFF, 1.0f);
    __syncthreads();

    // RoPE on q and k: (even,odd) pair rotation
    for (int i = tid; i < 4704; i += THREADS) {
        int d = i & 15, nh = i >> 4;
        int hh = nh % 6, n = nh / 6;
        int base = n * 192 + hh * 32 + 2 * d;
        float cv = sm[COS_OFF + i], sv = sm[SIN_OFF + i];
        float2 qu = *reinterpret_cast<float2*>(&sm[Q_OFF + base]);
        float2 ku = *reinterpret_cast<float2*>(&sm[K_OFF + base]);
        float2 qo = make_float2(qu.x * cv - qu.y * sv, qu.x * sv + qu.y * cv);
        float2 ko = make_float2(ku.x * cv - ku.y * sv, ku.x * sv + ku.y * cv);
        *reinterpret_cast<float2*>(&sm[Q_OFF + base]) = qo;
        *reinterpret_cast<float2*>(&sm[K_OFF + base]) = ko;
    }

    const float* mrow = mask + (size_t)(b & 63) * 2401;  // window = b % NW

    for (int hh = 0; hh < 6; hh++) {
        __syncthreads();  // rope done (h=0) / prev head's P@V read of LG done
        // logits[49][49] = q_h @ k_h^T + mask, 2x2 register tiles
        for (int bi = tid; bi < 625; bi += THREADS) {
            int ni = (bi / 25) * 2;
            int mi = (bi % 25) * 2;
            const float4* q0 = reinterpret_cast<const float4*>(&sm[Q_OFF + ni * 192 + hh * 32]);
            const float4* q1 = reinterpret_cast<const float4*>(&sm[Q_OFF + (ni + 1) * 192 + hh * 32]);
            const float4* k0 = reinterpret_cast<const float4*>(&sm[K_OFF + mi * 192 + hh * 32]);
            const float4* k1 = reinterpret_cast<const float4*>(&sm[K_OFF + (mi + 1) * 192 + hh * 32]);
            float a00 = 0.f, a01 = 0.f, a10 = 0.f, a11 = 0.f;
            #pragma unroll
            for (int d4 = 0; d4 < 8; d4++) {
                float4 qa = q0[d4], qb = q1[d4], ka = k0[d4], kb = k1[d4];
                a00 += qa.x * ka.x + qa.y * ka.y + qa.z * ka.z + qa.w * ka.w;
                a01 += qa.x * kb.x + qa.y * kb.y + qa.z * kb.z + qa.w * kb.w;
                a10 += qb.x * ka.x + qb.y * ka.y + qb.z * ka.z + qb.w * ka.w;
                a11 += qb.x * kb.x + qb.y * kb.y + qb.z * kb.z + qb.w * kb.w;
            }
            bool n1ok = (ni + 1) < 49;
            bool m1ok = (mi + 1) < 49;
            sm[LG_OFF + ni * LG_STRIDE + mi] = a00 + mrow[ni * 49 + mi];
            if (m1ok)         sm[LG_OFF + ni * LG_STRIDE + mi + 1]       = a01 + mrow[ni * 49 + mi + 1];
            if (n1ok)         sm[LG_OFF + (ni + 1) * LG_STRIDE + mi]     = a10 + mrow[(ni + 1) * 49 + mi];
            if (n1ok && m1ok) sm[LG_OFF + (ni + 1) * LG_STRIDE + mi + 1] = a11 + mrow[(ni + 1) * 49 + mi + 1];
        }
        __syncthreads();
        // softmax: one thread per row
        if (tid < 49) {
            float* row = &sm[LG_OFF + tid * LG_STRIDE];
            float mx = row[0];
            #pragma unroll 7
            for (int m = 1; m < 49; m++) mx = fmaxf(mx, row[m]);
            float s = 0.f;
            #pragma unroll 7
            for (int m = 0; m < 49; m++) { float e = __expf(row[m] - mx); row[m] = e; s += e; }
            float inv = 1.0f / s;
            #pragma unroll 7
            for (int m = 0; m < 49; m++) row[m] *= inv;
        }
        __syncthreads();
        // out_h[49][32] = P @ V_h  -> write into XO (x no longer needed)
        {
            int dp = tid & 15;   // d = 2*dp
            int nb = tid >> 4;
            #pragma unroll
            for (int t = 0; t < 4; t++) {
                int n = nb + 16 * t;
                if (n < 49) {
                    unsigned long long accv = 0ULL;
                    const float* pr = &sm[LG_OFF + n * LG_STRIDE];
                    const float* vp = &sm[V_OFF + hh * 32 + 2 * dp];
                    #pragma unroll 7
                    for (int m = 0; m < 49; m++) {
                        unsigned long long p2 = pk2(pr[m], pr[m]);
                        unsigned long long vv =
                            *reinterpret_cast<const unsigned long long*>(&vp[m * 192]);
                        fma2(accv, p2, vv);
                    }
                    float2 r = unpk2(accv);
                    *reinterpret_cast<float2*>(&sm[XO_OFF + n * 192 + hh * 32 + 2 * dp]) = r;
                }
            }
        }
    }

    // output projection: XO @ proj_w^T + proj_b -> reuse Q buffer
    gemm192(proj_w, proj_b, XO_OFF, Q_OFF, 1.0f);
    __syncthreads();
    {
        float4* og = reinterpret_cast<float4*>(out) + (size_t)b * 2352;
        const float4* qs = reinterpret_cast<const float4*>(&sm[Q_OFF]);
        for (int i = tid; i < 2352; i += THREADS) og[i] = qs[i];
    }
}

extern "C" void kernel_launch(void* const* d_in, const int* in_sizes, int n_in,
                              void* d_out, int out_size) {
    const float* x      = (const float*)d_in[0];
    const float* mask   = (const float*)d_in[1];
    const float* qkv_w  = (const float*)d_in[2];
    const float* qkv_b  = (const float*)d_in[3];
    const float* proj_w = (const float*)d_in[4];
    const float* proj_b = (const float*)d_in[5];
    const float* rope   = (const float*)d_in[6];
    float* out = (float*)d_out;

    cudaFuncSetAttribute(swin_fused_kernel,
                         cudaFuncAttributeMaxDynamicSharedMemorySize, SMEM_BYTES);
    swin_fused_kernel<<<4096, THREADS, SMEM_BYTES>>>(
        x, mask, qkv_w, qkv_b, proj_w, proj_b, rope, out);
}